// round 13
// baseline (speedup 1.0000x reference)
#include <cuda_runtime.h>
#include <cuda_bf16.h>
#include <math.h>
#include <stdint.h>

// ---------------- problem constants ----------------
#define HDIM   256
#define NL     6
#define NSTATE 64
#define DIN    512
#define HEADS  8
#define PDIM   64
#define CONVD  640          // DIN + 2*N
#define PROJ   1160         // full in-proj width (source layout)
#define ZROW   1152         // z(512) + xBC(640) -> GEMM output width, 9 tiles of 128
#define TOK    65536        // tokens per mamba call (128*512 == 1024*64)
#define XELEMS (2ull*512ull*64ull*HDIM)   // 16,777,216

// ---------------- scratch (device globals; no allocation allowed) ----------------
__device__ float g_bufA[XELEMS];
__device__ float g_bufB[XELEMS];
__device__ float g_zx [(size_t)TOK * ZROW];
__device__ float g_xbc[(size_t)TOK * CONVD];
__device__ float g_dt [(size_t)TOK * HEADS];
__device__ float g_dA [(size_t)TOK * HEADS];
__device__ __nv_bfloat16 g_xh[(size_t)TOK * DIN];
__device__ __nv_bfloat16 g_xl[(size_t)TOK * DIN];
__device__ __nv_bfloat16 g_WinTh [12][(size_t)ZROW * HDIM];
__device__ __nv_bfloat16 g_WinTl [12][(size_t)ZROW * HDIM];
__device__ __nv_bfloat16 g_WoutTh[12][(size_t)HDIM * DIN];
__device__ __nv_bfloat16 g_WoutTl[12][(size_t)HDIM * DIN];
__device__ float g_Wdt[12][(size_t)HDIM * HEADS];   // dt columns, [k][h] fp32

// ================= PTX helpers (baseline ISA only) =================
__device__ __forceinline__ uint32_t smem_u32(const void* p) {
    uint32_t a;
    asm("{ .reg .u64 t; cvta.to.shared.u64 t, %1; cvt.u32.u64 %0, t; }" : "=r"(a) : "l"(p));
    return a;
}
#define CP_ASYNC16(dst, src) \
    asm volatile("cp.async.cg.shared.global [%0], [%1], 16;" :: "r"(dst), "l"(src))
#define CP_COMMIT() asm volatile("cp.async.commit_group;" ::: "memory")
#define CP_WAIT0()  asm volatile("cp.async.wait_group 0;" ::: "memory")
#define CP_WAIT1()  asm volatile("cp.async.wait_group 1;" ::: "memory")
#define LDSM_X4(r0, r1, r2, r3, addr) \
    asm volatile("ldmatrix.sync.aligned.m8n8.x4.shared.b16 {%0,%1,%2,%3}, [%4];" \
        : "=r"(r0), "=r"(r1), "=r"(r2), "=r"(r3) : "r"(addr))
#define MMA_BF16(d, a, b) \
    asm volatile("mma.sync.aligned.m16n8k16.row.col.f32.bf16.bf16.f32 " \
        "{%0,%1,%2,%3}, {%4,%5,%6,%7}, {%8,%9}, {%0,%1,%2,%3};" \
        : "+f"((d)[0]), "+f"((d)[1]), "+f"((d)[2]), "+f"((d)[3]) \
        : "r"((a)[0]), "r"((a)[1]), "r"((a)[2]), "r"((a)[3]), \
          "r"((b)[0]), "r"((b)[1]))

__device__ __forceinline__ uint32_t swz(uint32_t off) { return off ^ ((off >> 3) & 0x70); }

// ================= bf16x3 HMMA GEMM =================
// C[M,N] = (Res?) + (Ah+Al)[M,K] @ (Bh+Bl)[N,K]^T, dropping Al*Bl.
// tile 128x128, K-chunk 64, cp.async 2-stage, 512 threads (4x4 warps, 32x32/warp).
#define GEMM_SMEM (2 * 65536)
__global__ __launch_bounds__(512, 1) void mma_gemm_k(int N, int K,
        const __nv_bfloat16* __restrict__ Ah, const __nv_bfloat16* __restrict__ Al,
        const __nv_bfloat16* __restrict__ Bh, const __nv_bfloat16* __restrict__ Bl,
        const float* __restrict__ Res, float* __restrict__ C)
{
    extern __shared__ __align__(1024) char smem[];
    uint32_t sb = smem_u32(smem);
    int tid  = threadIdx.x;
    int wid  = tid >> 5, lane = tid & 31;
    size_t row0 = (size_t)blockIdx.y * 128;
    size_t nr0  = (size_t)blockIdx.x * 128;
    int    n0   = blockIdx.x * 128;

    const __nv_bfloat16* mats[4] = { Ah, Al, Bh, Bl };
    const int NC = K >> 6;

    auto load_stage = [&](int c) {
        uint32_t st = sb + (uint32_t)(c & 1) * 65536;
        int kofs = c << 6;
#pragma unroll
        for (int m = 0; m < 4; ++m) {
            size_t rbase = (m < 2) ? row0 : nr0;
            const char* P = (const char*)(mats[m] + rbase * K + kofs);
            uint32_t dst = st + m * 16384;
#pragma unroll
            for (int i = 0; i < 2; ++i) {
                int seg = i * 512 + tid;           // 1024 16B segments per matrix
                int row = seg >> 3, sj = seg & 7;
                CP_ASYNC16(dst + swz(row * 128 + sj * 16),
                           P + (size_t)row * K * 2 + sj * 16);
            }
        }
        CP_COMMIT();
    };

    float acc[2][4][4];
#pragma unroll
    for (int i = 0; i < 2; ++i)
#pragma unroll
        for (int j = 0; j < 4; ++j)
#pragma unroll
            for (int q = 0; q < 4; ++q) acc[i][j][q] = 0.f;

    int wm = wid >> 2, wn = wid & 3;      // 4x4 warps
    int m0w = wm * 32, n0w = wn * 32;
    int lm = lane & 7;
    int li = lane >> 3;

    load_stage(0);
    for (int c = 0; c < NC; ++c) {
        bool pf = (c + 1 < NC);
        if (pf) load_stage(c + 1);
        if (pf) CP_WAIT1(); else CP_WAIT0();
        __syncthreads();

        uint32_t st  = sb + (uint32_t)(c & 1) * 65536;
        uint32_t aph = st, apl = st + 16384, bph = st + 32768, bpl = st + 49152;
#pragma unroll
        for (int k16 = 0; k16 < 4; ++k16) {
            uint32_t Ahf[2][4], Alf[2][4], Bhf[4][2], Blf[4][2];
            {
                int rA   = m0w + ((li & 1) << 3) + lm;
                int c16A = k16 * 2 + (li >> 1);
#pragma unroll
                for (int ma = 0; ma < 2; ++ma) {
                    uint32_t off = swz((uint32_t)(rA + ma * 16) * 128 + c16A * 16);
                    LDSM_X4(Ahf[ma][0], Ahf[ma][1], Ahf[ma][2], Ahf[ma][3], aph + off);
                    LDSM_X4(Alf[ma][0], Alf[ma][1], Alf[ma][2], Alf[ma][3], apl + off);
                }
            }
            {
                int rB   = n0w + ((li >> 1) << 3) + lm;
                int c16B = k16 * 2 + (li & 1);
#pragma unroll
                for (int nb = 0; nb < 2; ++nb) {
                    uint32_t off = swz((uint32_t)(rB + nb * 16) * 128 + c16B * 16);
                    LDSM_X4(Bhf[nb*2][0], Bhf[nb*2][1], Bhf[nb*2+1][0], Bhf[nb*2+1][1], bph + off);
                    LDSM_X4(Blf[nb*2][0], Blf[nb*2][1], Blf[nb*2+1][0], Blf[nb*2+1][1], bpl + off);
                }
            }
#pragma unroll
            for (int ma = 0; ma < 2; ++ma)
#pragma unroll
                for (int na = 0; na < 4; ++na) {
                    MMA_BF16(acc[ma][na], Ahf[ma], Bhf[na]);
                    MMA_BF16(acc[ma][na], Ahf[ma], Blf[na]);
                    MMA_BF16(acc[ma][na], Alf[ma], Bhf[na]);
                }
        }
        __syncthreads();
    }

    int gid = lane >> 2, tig = lane & 3;
#pragma unroll
    for (int ma = 0; ma < 2; ++ma) {
        size_t r0g = row0 + m0w + ma * 16 + gid;
#pragma unroll
        for (int na = 0; na < 4; ++na) {
            int cc = n0 + n0w + na * 8 + tig * 2;
            float2 v0 = make_float2(acc[ma][na][0], acc[ma][na][1]);
            float2 v1 = make_float2(acc[ma][na][2], acc[ma][na][3]);
            if (Res) {
                float2 r0v = *(const float2*)&Res[r0g * N + cc];
                float2 r1v = *(const float2*)&Res[(r0g + 8) * N + cc];
                v0.x += r0v.x; v0.y += r0v.y; v1.x += r1v.x; v1.y += r1v.y;
            }
            *(float2*)&C[r0g * N + cc]       = v0;
            *(float2*)&C[(r0g + 8) * N + cc] = v1;
        }
    }
}

// ------- weight prep: exactly 2 launches -------
__global__ __launch_bounds__(256) void wtrans_win_k(const float* __restrict__ Wt,
                                                    const float* __restrict__ Wb,
                                                    __nv_bfloat16* __restrict__ WTh,
                                                    __nv_bfloat16* __restrict__ WTl)
{
    size_t idx = (size_t)blockIdx.x * 256 + threadIdx.x;
    if (idx >= 12ull * ZROW * HDIM) return;
    int li  = (int)(idx / ((size_t)ZROW * HDIM));
    int rem = (int)(idx % ((size_t)ZROW * HDIM));
    int n = rem / HDIM, k = rem % HDIM;
    const float* W = (li < 6) ? (Wt + (size_t)li * HDIM * PROJ)
                              : (Wb + (size_t)(li - 6) * HDIM * PROJ);
    float v = W[(size_t)k * PROJ + n];
    __nv_bfloat16 h = __float2bfloat16(v);
    WTh[idx] = h;
    WTl[idx] = __float2bfloat16(v - __bfloat162float(h));
}
__global__ __launch_bounds__(256) void wtrans_misc_k(const float* __restrict__ WtO,
                                                     const float* __restrict__ WbO,
                                                     const float* __restrict__ WtI,
                                                     const float* __restrict__ WbI,
                                                     __nv_bfloat16* __restrict__ WTh,
                                                     __nv_bfloat16* __restrict__ WTl,
                                                     float* __restrict__ Wdt)
{
    size_t woutTot = 12ull * HDIM * DIN;
    size_t idx = (size_t)blockIdx.x * 256 + threadIdx.x;
    if (idx < woutTot) {
        int li  = (int)(idx / ((size_t)HDIM * DIN));
        int rem = (int)(idx % ((size_t)HDIM * DIN));
        int n = rem / DIN, k = rem % DIN;
        const float* W = (li < 6) ? (WtO + (size_t)li * DIN * HDIM)
                                  : (WbO + (size_t)(li - 6) * DIN * HDIM);
        float v = W[(size_t)k * HDIM + n];
        __nv_bfloat16 h = __float2bfloat16(v);
        WTh[idx] = h;
        WTl[idx] = __float2bfloat16(v - __bfloat162float(h));
    } else {
        size_t j = idx - woutTot;
        if (j >= 12ull * HDIM * HEADS) return;
        int li  = (int)(j / (HDIM * HEADS));
        int rem = (int)(j % (HDIM * HEADS));
        int k = rem / HEADS, h = rem % HEADS;
        const float* W = (li < 6) ? (WtI + (size_t)li * HDIM * PROJ)
                                  : (WbI + (size_t)(li - 6) * HDIM * PROJ);
        Wdt[j] = W[(size_t)k * PROJ + ZROW + h];
    }
}

// ------ rmsnorm-256 -> bf16 hi/lo  +  fused dt/dA (fp32 GEMV over 8 cols) ------
__global__ __launch_bounds__(256) void rms256_k(const float* __restrict__ x,
                                                const float* __restrict__ w,
                                                const float* __restrict__ Wdt,
                                                const float* __restrict__ dtb,
                                                const float* __restrict__ Alog,
                                                __nv_bfloat16* __restrict__ oh,
                                                __nv_bfloat16* __restrict__ ol,
                                                float* __restrict__ odt,
                                                float* __restrict__ odA)
{
    int warp = (blockIdx.x * blockDim.x + threadIdx.x) >> 5;   // token
    int lane = threadIdx.x & 31;
    const float* row = x + (size_t)warp * HDIM;
    float v[8]; float ss = 0.f;
#pragma unroll
    for (int i = 0; i < 8; i++) { v[i] = row[lane + i*32]; ss += v[i]*v[i]; }
#pragma unroll
    for (int o = 16; o > 0; o >>= 1) ss += __shfl_xor_sync(0xffffffffu, ss, o);
    float rs = rsqrtf(ss * (1.f/256.f) + 1e-6f);
    __nv_bfloat16* hrow = oh + (size_t)warp * HDIM;
    __nv_bfloat16* lrow = ol + (size_t)warp * HDIM;
    float ph[8];
#pragma unroll
    for (int q = 0; q < 8; q++) ph[q] = 0.f;
#pragma unroll
    for (int i = 0; i < 8; i++) {
        int c = lane + i*32;
        float f = v[i] * rs * w[c];
        __nv_bfloat16 h = __float2bfloat16(f);
        hrow[c] = h;
        lrow[c] = __float2bfloat16(f - __bfloat162float(h));
        const float* wd = Wdt + c * HEADS;
        float4 wa = *(const float4*)wd;
        float4 wb = *(const float4*)(wd + 4);
        ph[0] = fmaf(f, wa.x, ph[0]); ph[1] = fmaf(f, wa.y, ph[1]);
        ph[2] = fmaf(f, wa.z, ph[2]); ph[3] = fmaf(f, wa.w, ph[3]);
        ph[4] = fmaf(f, wb.x, ph[4]); ph[5] = fmaf(f, wb.y, ph[5]);
        ph[6] = fmaf(f, wb.z, ph[6]); ph[7] = fmaf(f, wb.w, ph[7]);
    }
#pragma unroll
    for (int o = 16; o > 0; o >>= 1)
#pragma unroll
        for (int q = 0; q < 8; q++) ph[q] += __shfl_xor_sync(0xffffffffu, ph[q], o);
    if (lane == 0) {
#pragma unroll
        for (int q = 0; q < 8; q++) {
            float raw = ph[q] + dtb[q];
            float sp  = (raw > 20.f) ? raw : log1pf(expf(raw));
            odt[(size_t)warp * HEADS + q] = sp;
            odA[(size_t)warp * HEADS + q] = expf(-expf(Alog[q]) * sp);
        }
    }
}

// ------- causal depthwise conv (k=4) + SiLU, parallel over 64-step L-chunks -------
__global__ __launch_bounds__(128) void conv_k(const float* __restrict__ zx,
                                              const float* __restrict__ cw,
                                              const float* __restrict__ cb,
                                              float* __restrict__ xbc,
                                              int L, int nch)
{
    int bx = blockIdx.x;
    int s  = bx / nch;
    int ch = bx - s * nch;
    int c  = blockIdx.y * 128 + threadIdx.x;      // 0..639
    int l0 = ch * 64;
    float w0 = cw[c], w1 = cw[640 + c], w2 = cw[1280 + c], w3 = cw[1920 + c];
    float bias = cb[c];
    const float* in  = zx  + ((size_t)s * L + l0) * ZROW + DIN + c;
    float*       out = xbc + ((size_t)s * L + l0) * CONVD + c;
    float x0 = (l0 > 0) ? in[-3 * ZROW] : 0.f;
    float x1 = (l0 > 0) ? in[-2 * ZROW] : 0.f;
    float x2 = (l0 > 0) ? in[-1 * ZROW] : 0.f;
    for (int l = 0; l < 64; ++l) {
        float x3 = in[(size_t)l * ZROW];
        float v  = bias + w0*x0 + w1*x1 + w2*x2 + w3*x3;
        out[(size_t)l * CONVD] = v / (1.f + __expf(-v));
        x0 = x1; x1 = x2; x2 = x3;
    }
}

// -- SSM scan + FUSED gate/rmsnorm-512 -> bf16 hi/lo : one CTA per sequence --
__global__ __launch_bounds__(512, 1) void scan_gate_k(const float* __restrict__ xbc,
                                                      const float* __restrict__ dt,
                                                      const float* __restrict__ dA,
                                                      const float* __restrict__ Dp,
                                                      const float* __restrict__ zx,
                                                      const float* __restrict__ gn,
                                                      __nv_bfloat16* __restrict__ oh,
                                                      __nv_bfloat16* __restrict__ ol,
                                                      int L)
{
    int s   = blockIdx.x;
    int tid = threadIdx.x;
    int wid = tid >> 5, lane = tid & 31;
    int hh  = tid >> 6;
    __shared__ float sB[2][64], sC[2][64], sdt[2][8], sdA[2][8], sred[16];
    float h[64];
#pragma unroll
    for (int n = 0; n < 64; n++) h[n] = 0.f;
    float Dh  = Dp[hh];
    float gnv = gn[tid];
    size_t base = (size_t)s * L;

    // preload step 0
    float pf_x   = xbc[base * CONVD + tid];
    float pf_z   = zx[base * ZROW + tid];
    float pf_aux = 0.f;
    if (tid < 128)       pf_aux = xbc[base * CONVD + DIN + tid];
    else if (tid < 136)  pf_aux = dt[base * HEADS + (tid - 128)];
    else if (tid < 144)  pf_aux = dA[base * HEADS + (tid - 136)];

    for (int l = 0; l < L; ++l) {
        int buf = l & 1;
        if (tid < 64)        sB[buf][tid] = pf_aux;
        else if (tid < 128)  sC[buf][tid - 64] = pf_aux;
        else if (tid < 136)  sdt[buf][tid - 128] = pf_aux;
        else if (tid < 144)  sdA[buf][tid - 136] = pf_aux;
        float xv = pf_x;
        float zv = pf_z;
        __syncthreads();
        // prefetch step l+1 while computing step l
        if (l + 1 < L) {
            size_t nb = base + l + 1;
            pf_x = xbc[nb * CONVD + tid];
            pf_z = zx[nb * ZROW + tid];
            if (tid < 128)       pf_aux = xbc[nb * CONVD + DIN + tid];
            else if (tid < 136)  pf_aux = dt[nb * HEADS + (tid - 128)];
            else if (tid < 144)  pf_aux = dA[nb * HEADS + (tid - 136)];
        }
        float a   = sdA[buf][hh];
        float xdt = xv * sdt[buf][hh];
        float acc0 = 0.f, acc1 = 0.f, acc2 = 0.f, acc3 = 0.f;
#pragma unroll
        for (int n4 = 0; n4 < 16; ++n4) {
            float4 b4 = *(const float4*)&sB[buf][n4 * 4];
            float4 c4 = *(const float4*)&sC[buf][n4 * 4];
            int n = n4 * 4;
            h[n+0] = fmaf(a, h[n+0], xdt * b4.x); acc0 = fmaf(h[n+0], c4.x, acc0);
            h[n+1] = fmaf(a, h[n+1], xdt * b4.y); acc1 = fmaf(h[n+1], c4.y, acc1);
            h[n+2] = fmaf(a, h[n+2], xdt * b4.z); acc2 = fmaf(h[n+2], c4.z, acc2);
            h[n+3] = fmaf(a, h[n+3], xdt * b4.w); acc3 = fmaf(h[n+3], c4.w, acc3);
        }
        float yv = ((acc0 + acc1) + (acc2 + acc3)) + Dh * xv;
        // fused gate + rmsnorm-512 over the CTA's 512 channels
        float gv = yv * (zv / (1.f + __expf(-zv)));
        float ss = gv * gv;
#pragma unroll
        for (int o = 16; o > 0; o >>= 1) ss += __shfl_xor_sync(0xffffffffu, ss, o);
        if (lane == 0) sred[wid] = ss;
        __syncthreads();
        float tot = 0.f;
#pragma unroll
        for (int q = 0; q < 16; ++q) tot += sred[q];
        float rs = rsqrtf(tot * (1.f/512.f) + 1e-6f);
        float f  = gv * rs * gnv;
        __nv_bfloat16 fh = __float2bfloat16(f);
        size_t oidx = (base + l) * DIN + tid;
        oh[oidx] = fh;
        ol[oidx] = __float2bfloat16(f - __bfloat162float(fh));
    }
}

// ---------------- transpose (2,64,512,H) -> (2,512,64,H) ----------------
__global__ __launch_bounds__(256) void transpose_k(const float* __restrict__ in,
                                                   float* __restrict__ out)
{
    size_t id = (size_t)blockIdx.x * 256 + threadIdx.x;
    int h4   = (int)(id & 63);
    int band = (int)((id >> 6) & 63);
    int t    = (int)((id >> 12) & 511);
    int b    = (int)(id >> 21);
    const float4* ip = (const float4*)in;
    ((float4*)out)[id] = ip[((((size_t)(b * 64 + band)) * 512 + t) << 6) + h4];
}

// ---------------- host-side orchestration ----------------
static void run_mamba(const float* io_in, float* io_out, int S, int L,
                      const float* norm, const float* Wdt,
                      const __nv_bfloat16* WinTh, const __nv_bfloat16* WinTl,
                      const float* cw, const float* cb, const float* dtb,
                      const float* Alog, const float* Dp, const float* gn,
                      const __nv_bfloat16* WoutTh, const __nv_bfloat16* WoutTl,
                      __nv_bfloat16* xh, __nv_bfloat16* xl,
                      float* zx, float* xbc, float* dtp, float* dAp)
{
    rms256_k<<<TOK / 8, 256>>>(io_in, norm, Wdt, dtb, Alog, xh, xl, dtp, dAp);
    {
        dim3 grid(ZROW / 128, TOK / 128);
        mma_gemm_k<<<grid, 512, GEMM_SMEM>>>(ZROW, HDIM, xh, xl, WinTh, WinTl, nullptr, zx);
    }
    {
        int nch = L / 64;
        dim3 grid(S * nch, CONVD / 128);
        conv_k<<<grid, 128>>>(zx, cw, cb, xbc, L, nch);
    }
    scan_gate_k<<<S, 512>>>(xbc, dtp, dAp, Dp, zx, gn, xh, xl, L);
    {
        dim3 grid(HDIM / 128, TOK / 128);
        mma_gemm_k<<<grid, 512, GEMM_SMEM>>>(HDIM, DIN, xh, xl, WoutTh, WoutTl, io_in, io_out);
    }
}

extern "C" void kernel_launch(void* const* d_in, const int* in_sizes, int n_in,
                              void* d_out, int out_size)
{
    const float* x = (const float*)d_in[0];
    const float* prm[2][9];
    for (int pth = 0; pth < 2; ++pth)
        for (int j = 0; j < 9; ++j)
            prm[pth][j] = (const float*)d_in[1 + pth * 9 + j];
    // order per path: norm, Win, cw, cb, dtb, Alog, D, gn, Wout

    cudaFuncSetAttribute(mma_gemm_k, cudaFuncAttributeMaxDynamicSharedMemorySize, GEMM_SMEM);

    float *bufA, *bufB, *zx, *xbc, *dtp, *dAp, *Wdt;
    __nv_bfloat16 *xh, *xl, *WinTh, *WinTl, *WoutTh, *WoutTl;
    cudaGetSymbolAddress((void**)&bufA, g_bufA);
    cudaGetSymbolAddress((void**)&bufB, g_bufB);
    cudaGetSymbolAddress((void**)&zx,  g_zx);
    cudaGetSymbolAddress((void**)&xbc, g_xbc);
    cudaGetSymbolAddress((void**)&dtp, g_dt);
    cudaGetSymbolAddress((void**)&dAp, g_dA);
    cudaGetSymbolAddress((void**)&xh,  g_xh);
    cudaGetSymbolAddress((void**)&xl,  g_xl);
    cudaGetSymbolAddress((void**)&WinTh,  g_WinTh);
    cudaGetSymbolAddress((void**)&WinTl,  g_WinTl);
    cudaGetSymbolAddress((void**)&WoutTh, g_WoutTh);
    cudaGetSymbolAddress((void**)&WoutTl, g_WoutTl);
    cudaGetSymbolAddress((void**)&Wdt, g_Wdt);

    // weight prep: 2 launches => rms256 is my #3, in-proj GEMM my #4 (ncu target)
    {
        size_t tot = 12ull * ZROW * HDIM;
        wtrans_win_k<<<(unsigned)((tot + 255) / 256), 256>>>(prm[0][1], prm[1][1], WinTh, WinTl);
    }
    {
        size_t tot = 12ull * HDIM * DIN + 12ull * HDIM * HEADS;
        wtrans_misc_k<<<(unsigned)((tot + 255) / 256), 256>>>(
            prm[0][8], prm[1][8], prm[0][1], prm[1][1], WoutTh, WoutTl, Wdt);
    }

    float* cur = bufA;
    float* alt = bufB;
    const size_t nF4 = XELEMS / 4;

    for (int i = 0; i < NL; ++i) {
        // time path: 128 contiguous sequences of 512 tokens
        const float* tin = (i == 0) ? x : cur;
        run_mamba(tin, cur, 128, 512,
                  prm[0][0] + (size_t)i * HDIM,
                  Wdt + (size_t)(0 * NL + i) * HDIM * HEADS,
                  WinTh + (size_t)(0 * NL + i) * ZROW * HDIM,
                  WinTl + (size_t)(0 * NL + i) * ZROW * HDIM,
                  prm[0][2] + (size_t)i * 4 * CONVD,
                  prm[0][3] + (size_t)i * CONVD,
                  prm[0][4] + (size_t)i * HEADS,
                  prm[0][5] + (size_t)i * HEADS,
                  prm[0][6] + (size_t)i * HEADS,
                  prm[0][7] + (size_t)i * DIN,
                  WoutTh + (size_t)(0 * NL + i) * HDIM * DIN,
                  WoutTl + (size_t)(0 * NL + i) * HDIM * DIN,
                  xh, xl, zx, xbc, dtp, dAp);

        transpose_k<<<(unsigned)(nF4 / 256), 256>>>(cur, alt);
        { float* tmp = cur; cur = alt; alt = tmp; }

        // band path: 1024 contiguous sequences of 64 tokens
        float* bout = (i == NL - 1) ? (float*)d_out : cur;
        run_mamba(cur, bout, 1024, 64,
                  prm[1][0] + (size_t)i * HDIM,
                  Wdt + (size_t)(1 * NL + i) * HDIM * HEADS,
                  WinTh + (size_t)(1 * NL + i) * ZROW * HDIM,
                  WinTl + (size_t)(1 * NL + i) * ZROW * HDIM,
                  prm[1][2] + (size_t)i * 4 * CONVD,
                  prm[1][3] + (size_t)i * CONVD,
                  prm[1][4] + (size_t)i * HEADS,
                  prm[1][5] + (size_t)i * HEADS,
                  prm[1][6] + (size_t)i * HEADS,
                  prm[1][7] + (size_t)i * DIN,
                  WoutTh + (size_t)(1 * NL + i) * HDIM * DIN,
                  WoutTl + (size_t)(1 * NL + i) * HDIM * DIN,
                  xh, xl, zx, xbc, dtp, dAp);
    }
}

// round 15
// speedup vs baseline: 1.0965x; 1.0965x over previous
#include <cuda_runtime.h>
#include <cuda_bf16.h>
#include <math.h>
#include <stdint.h>

// ---------------- problem constants ----------------
#define HDIM   256
#define NL     6
#define NSTATE 64
#define DIN    512
#define HEADS  8
#define PDIM   64
#define CONVD  640          // DIN + 2*N
#define PROJ   1160         // full in-proj width (source layout)
#define ZROW   1152         // z(512) + xBC(640) -> GEMM output width, 9 tiles of 128
#define TOK    65536        // tokens per mamba call (128*512 == 1024*64)
#define XELEMS (2ull*512ull*64ull*HDIM)   // 16,777,216

// ---------------- scratch (device globals; no allocation allowed) ----------------
__device__ float g_bufA[XELEMS];
__device__ float g_bufB[XELEMS];
__device__ float g_zx [(size_t)TOK * ZROW];
__device__ float g_xbc[(size_t)TOK * CONVD];
__device__ float g_dt [(size_t)TOK * HEADS];
__device__ float g_dA [(size_t)TOK * HEADS];
__device__ float g_y  [(size_t)TOK * DIN];
__device__ __nv_bfloat16 g_xh[(size_t)TOK * DIN];
__device__ __nv_bfloat16 g_xl[(size_t)TOK * DIN];
__device__ __nv_bfloat16 g_WinTh [12][(size_t)ZROW * HDIM];
__device__ __nv_bfloat16 g_WinTl [12][(size_t)ZROW * HDIM];
__device__ __nv_bfloat16 g_WoutTh[12][(size_t)HDIM * DIN];
__device__ __nv_bfloat16 g_WoutTl[12][(size_t)HDIM * DIN];
__device__ float g_Wdt[12][(size_t)HDIM * HEADS];   // dt columns, [k][h] fp32

// ================= PTX helpers (baseline ISA only) =================
__device__ __forceinline__ uint32_t smem_u32(const void* p) {
    uint32_t a;
    asm("{ .reg .u64 t; cvta.to.shared.u64 t, %1; cvt.u32.u64 %0, t; }" : "=r"(a) : "l"(p));
    return a;
}
#define CP_ASYNC16(dst, src) \
    asm volatile("cp.async.cg.shared.global [%0], [%1], 16;" :: "r"(dst), "l"(src))
#define CP_COMMIT() asm volatile("cp.async.commit_group;" ::: "memory")
#define CP_WAIT0()  asm volatile("cp.async.wait_group 0;" ::: "memory")
#define CP_WAIT1()  asm volatile("cp.async.wait_group 1;" ::: "memory")
#define LDSM_X4(r0, r1, r2, r3, addr) \
    asm volatile("ldmatrix.sync.aligned.m8n8.x4.shared.b16 {%0,%1,%2,%3}, [%4];" \
        : "=r"(r0), "=r"(r1), "=r"(r2), "=r"(r3) : "r"(addr))
#define MMA_BF16(d, a, b) \
    asm volatile("mma.sync.aligned.m16n8k16.row.col.f32.bf16.bf16.f32 " \
        "{%0,%1,%2,%3}, {%4,%5,%6,%7}, {%8,%9}, {%0,%1,%2,%3};" \
        : "+f"((d)[0]), "+f"((d)[1]), "+f"((d)[2]), "+f"((d)[3]) \
        : "r"((a)[0]), "r"((a)[1]), "r"((a)[2]), "r"((a)[3]), \
          "r"((b)[0]), "r"((b)[1]))

__device__ __forceinline__ uint32_t swz(uint32_t off) { return off ^ ((off >> 3) & 0x70); }

// ================= bf16x3 HMMA GEMM =================
// C[M,N] = (Res?) + (Ah+Al)[M,K] @ (Bh+Bl)[N,K]^T, dropping Al*Bl.
// tile 128x128, K-chunk 64, cp.async 2-stage, 256 threads (2x4 warps, 64x32/warp).
// Pass loop OUTERMOST: the three MMAs touching one acc are separated by 15
// independent MMAs -> no exposed accumulator RAW chains on the tensor pipe.
#define GEMM_SMEM (2 * 65536)
__global__ __launch_bounds__(256, 1) void mma_gemm_k(int N, int K,
        const __nv_bfloat16* __restrict__ Ah, const __nv_bfloat16* __restrict__ Al,
        const __nv_bfloat16* __restrict__ Bh, const __nv_bfloat16* __restrict__ Bl,
        const float* __restrict__ Res, float* __restrict__ C)
{
    extern __shared__ __align__(1024) char smem[];
    uint32_t sb = smem_u32(smem);
    int tid  = threadIdx.x;
    int wid  = tid >> 5, lane = tid & 31;
    size_t row0 = (size_t)blockIdx.y * 128;
    size_t nr0  = (size_t)blockIdx.x * 128;
    int    n0   = blockIdx.x * 128;

    const __nv_bfloat16* mats[4] = { Ah, Al, Bh, Bl };
    const int NC = K >> 6;

    auto load_stage = [&](int c) {
        uint32_t st = sb + (uint32_t)(c & 1) * 65536;
        int kofs = c << 6;
#pragma unroll
        for (int m = 0; m < 4; ++m) {
            size_t rbase = (m < 2) ? row0 : nr0;
            const char* P = (const char*)(mats[m] + rbase * K + kofs);
            uint32_t dst = st + m * 16384;
#pragma unroll
            for (int i = 0; i < 4; ++i) {
                int seg = i * 256 + tid;
                int row = seg >> 3, sj = seg & 7;
                CP_ASYNC16(dst + swz(row * 128 + sj * 16),
                           P + (size_t)row * K * 2 + sj * 16);
            }
        }
        CP_COMMIT();
    };

    float acc[4][4][4];
#pragma unroll
    for (int i = 0; i < 4; ++i)
#pragma unroll
        for (int j = 0; j < 4; ++j)
#pragma unroll
            for (int q = 0; q < 4; ++q) acc[i][j][q] = 0.f;

    int wm = wid >> 2, wn = wid & 3;      // warps 2(m) x 4(n)
    int m0w = wm * 64, n0w = wn * 32;
    int lm = lane & 7;
    int li = lane >> 3;

    load_stage(0);
    for (int c = 0; c < NC; ++c) {
        bool pf = (c + 1 < NC);
        if (pf) load_stage(c + 1);
        if (pf) CP_WAIT1(); else CP_WAIT0();
        __syncthreads();

        uint32_t st  = sb + (uint32_t)(c & 1) * 65536;
        uint32_t aph = st, apl = st + 16384, bph = st + 32768, bpl = st + 49152;
#pragma unroll
        for (int k16 = 0; k16 < 4; ++k16) {
            uint32_t Ahf[4][4], Alf[4][4], Bhf[4][2], Blf[4][2];
            {
                int rA   = m0w + ((li & 1) << 3) + lm;
                int c16A = k16 * 2 + (li >> 1);
#pragma unroll
                for (int ma = 0; ma < 4; ++ma) {
                    uint32_t off = swz((uint32_t)(rA + ma * 16) * 128 + c16A * 16);
                    LDSM_X4(Ahf[ma][0], Ahf[ma][1], Ahf[ma][2], Ahf[ma][3], aph + off);
                    LDSM_X4(Alf[ma][0], Alf[ma][1], Alf[ma][2], Alf[ma][3], apl + off);
                }
            }
            {
                int rB   = n0w + ((li >> 1) << 3) + lm;
                int c16B = k16 * 2 + (li & 1);
#pragma unroll
                for (int nb = 0; nb < 2; ++nb) {
                    uint32_t off = swz((uint32_t)(rB + nb * 16) * 128 + c16B * 16);
                    LDSM_X4(Bhf[nb*2][0], Bhf[nb*2][1], Bhf[nb*2+1][0], Bhf[nb*2+1][1], bph + off);
                    LDSM_X4(Blf[nb*2][0], Blf[nb*2][1], Blf[nb*2+1][0], Blf[nb*2+1][1], bpl + off);
                }
            }
            // pass 1: Ah x Bh  (16 independent MMAs)
#pragma unroll
            for (int ma = 0; ma < 4; ++ma)
#pragma unroll
                for (int na = 0; na < 4; ++na)
                    MMA_BF16(acc[ma][na], Ahf[ma], Bhf[na]);
            // pass 2: Ah x Bl
#pragma unroll
            for (int ma = 0; ma < 4; ++ma)
#pragma unroll
                for (int na = 0; na < 4; ++na)
                    MMA_BF16(acc[ma][na], Ahf[ma], Blf[na]);
            // pass 3: Al x Bh
#pragma unroll
            for (int ma = 0; ma < 4; ++ma)
#pragma unroll
                for (int na = 0; na < 4; ++na)
                    MMA_BF16(acc[ma][na], Alf[ma], Bhf[na]);
        }
        __syncthreads();
    }

    int gid = lane >> 2, tig = lane & 3;
#pragma unroll
    for (int ma = 0; ma < 4; ++ma) {
        size_t r0g = row0 + m0w + ma * 16 + gid;
#pragma unroll
        for (int na = 0; na < 4; ++na) {
            int cc = n0 + n0w + na * 8 + tig * 2;
            float2 v0 = make_float2(acc[ma][na][0], acc[ma][na][1]);
            float2 v1 = make_float2(acc[ma][na][2], acc[ma][na][3]);
            if (Res) {
                float2 r0v = *(const float2*)&Res[r0g * N + cc];
                float2 r1v = *(const float2*)&Res[(r0g + 8) * N + cc];
                v0.x += r0v.x; v0.y += r0v.y; v1.x += r1v.x; v1.y += r1v.y;
            }
            *(float2*)&C[r0g * N + cc]       = v0;
            *(float2*)&C[(r0g + 8) * N + cc] = v1;
        }
    }
}

// ------- weight prep: exactly 2 launches -------
__global__ __launch_bounds__(256) void wtrans_win_k(const float* __restrict__ Wt,
                                                    const float* __restrict__ Wb,
                                                    __nv_bfloat16* __restrict__ WTh,
                                                    __nv_bfloat16* __restrict__ WTl)
{
    size_t idx = (size_t)blockIdx.x * 256 + threadIdx.x;
    if (idx >= 12ull * ZROW * HDIM) return;
    int li  = (int)(idx / ((size_t)ZROW * HDIM));
    int rem = (int)(idx % ((size_t)ZROW * HDIM));
    int n = rem / HDIM, k = rem % HDIM;
    const float* W = (li < 6) ? (Wt + (size_t)li * HDIM * PROJ)
                              : (Wb + (size_t)(li - 6) * HDIM * PROJ);
    float v = W[(size_t)k * PROJ + n];
    __nv_bfloat16 h = __float2bfloat16(v);
    WTh[idx] = h;
    WTl[idx] = __float2bfloat16(v - __bfloat162float(h));
}
__global__ __launch_bounds__(256) void wtrans_misc_k(const float* __restrict__ WtO,
                                                     const float* __restrict__ WbO,
                                                     const float* __restrict__ WtI,
                                                     const float* __restrict__ WbI,
                                                     __nv_bfloat16* __restrict__ WTh,
                                                     __nv_bfloat16* __restrict__ WTl,
                                                     float* __restrict__ Wdt)
{
    size_t woutTot = 12ull * HDIM * DIN;
    size_t idx = (size_t)blockIdx.x * 256 + threadIdx.x;
    if (idx < woutTot) {
        int li  = (int)(idx / ((size_t)HDIM * DIN));
        int rem = (int)(idx % ((size_t)HDIM * DIN));
        int n = rem / DIN, k = rem % DIN;
        const float* W = (li < 6) ? (WtO + (size_t)li * DIN * HDIM)
                                  : (WbO + (size_t)(li - 6) * DIN * HDIM);
        float v = W[(size_t)k * HDIM + n];
        __nv_bfloat16 h = __float2bfloat16(v);
        WTh[idx] = h;
        WTl[idx] = __float2bfloat16(v - __bfloat162float(h));
    } else {
        size_t j = idx - woutTot;
        if (j >= 12ull * HDIM * HEADS) return;
        int li  = (int)(j / (HDIM * HEADS));
        int rem = (int)(j % (HDIM * HEADS));
        int k = rem / HEADS, h = rem % HEADS;
        const float* W = (li < 6) ? (WtI + (size_t)li * HDIM * PROJ)
                                  : (WbI + (size_t)(li - 6) * HDIM * PROJ);
        Wdt[j] = W[(size_t)k * PROJ + ZROW + h];
    }
}

// ------ rmsnorm-256 -> bf16 hi/lo  +  fused dt/dA (fp32 GEMV over 8 cols) ------
__global__ __launch_bounds__(256) void rms256_k(const float* __restrict__ x,
                                                const float* __restrict__ w,
                                                const float* __restrict__ Wdt,
                                                const float* __restrict__ dtb,
                                                const float* __restrict__ Alog,
                                                __nv_bfloat16* __restrict__ oh,
                                                __nv_bfloat16* __restrict__ ol,
                                                float* __restrict__ odt,
                                                float* __restrict__ odA)
{
    int warp = (blockIdx.x * blockDim.x + threadIdx.x) >> 5;   // token
    int lane = threadIdx.x & 31;
    const float* row = x + (size_t)warp * HDIM;
    float v[8]; float ss = 0.f;
#pragma unroll
    for (int i = 0; i < 8; i++) { v[i] = row[lane + i*32]; ss += v[i]*v[i]; }
#pragma unroll
    for (int o = 16; o > 0; o >>= 1) ss += __shfl_xor_sync(0xffffffffu, ss, o);
    float rs = rsqrtf(ss * (1.f/256.f) + 1e-6f);
    __nv_bfloat16* hrow = oh + (size_t)warp * HDIM;
    __nv_bfloat16* lrow = ol + (size_t)warp * HDIM;
    float ph[8];
#pragma unroll
    for (int q = 0; q < 8; q++) ph[q] = 0.f;
#pragma unroll
    for (int i = 0; i < 8; i++) {
        int c = lane + i*32;
        float f = v[i] * rs * w[c];
        __nv_bfloat16 h = __float2bfloat16(f);
        hrow[c] = h;
        lrow[c] = __float2bfloat16(f - __bfloat162float(h));
        const float* wd = Wdt + c * HEADS;
        float4 wa = *(const float4*)wd;
        float4 wb = *(const float4*)(wd + 4);
        ph[0] = fmaf(f, wa.x, ph[0]); ph[1] = fmaf(f, wa.y, ph[1]);
        ph[2] = fmaf(f, wa.z, ph[2]); ph[3] = fmaf(f, wa.w, ph[3]);
        ph[4] = fmaf(f, wb.x, ph[4]); ph[5] = fmaf(f, wb.y, ph[5]);
        ph[6] = fmaf(f, wb.z, ph[6]); ph[7] = fmaf(f, wb.w, ph[7]);
    }
#pragma unroll
    for (int o = 16; o > 0; o >>= 1)
#pragma unroll
        for (int q = 0; q < 8; q++) ph[q] += __shfl_xor_sync(0xffffffffu, ph[q], o);
    if (lane == 0) {
#pragma unroll
        for (int q = 0; q < 8; q++) {
            float raw = ph[q] + dtb[q];
            float sp  = (raw > 20.f) ? raw : log1pf(expf(raw));
            odt[(size_t)warp * HEADS + q] = sp;
            odA[(size_t)warp * HEADS + q] = expf(-expf(Alog[q]) * sp);
        }
    }
}

// ------- causal depthwise conv (k=4) + SiLU, parallel over 64-step L-chunks -------
__global__ __launch_bounds__(128) void conv_k(const float* __restrict__ zx,
                                              const float* __restrict__ cw,
                                              const float* __restrict__ cb,
                                              float* __restrict__ xbc,
                                              int L, int nch)
{
    int bx = blockIdx.x;
    int s  = bx / nch;
    int ch = bx - s * nch;
    int c  = blockIdx.y * 128 + threadIdx.x;      // 0..639
    int l0 = ch * 64;
    float w0 = cw[c], w1 = cw[640 + c], w2 = cw[1280 + c], w3 = cw[1920 + c];
    float bias = cb[c];
    const float* in  = zx  + ((size_t)s * L + l0) * ZROW + DIN + c;
    float*       out = xbc + ((size_t)s * L + l0) * CONVD + c;
    float x0 = (l0 > 0) ? in[-3 * ZROW] : 0.f;
    float x1 = (l0 > 0) ? in[-2 * ZROW] : 0.f;
    float x2 = (l0 > 0) ? in[-1 * ZROW] : 0.f;
    for (int l = 0; l < 64; ++l) {
        float x3 = in[(size_t)l * ZROW];
        float v  = bias + w0*x0 + w1*x1 + w2*x2 + w3*x3;
        out[(size_t)l * CONVD] = v / (1.f + __expf(-v));
        x0 = x1; x1 = x2; x2 = x3;
    }
}

// ------- SSM scan with next-step prefetch : one CTA per sequence -------
__global__ __launch_bounds__(512, 1) void scan_k(const float* __restrict__ xbc,
                                                 const float* __restrict__ dt,
                                                 const float* __restrict__ dA,
                                                 const float* __restrict__ Dp,
                                                 float* __restrict__ y,
                                                 int L)
{
    int s   = blockIdx.x;
    int tid = threadIdx.x;
    int hh  = tid >> 6;
    __shared__ float sB[2][64], sC[2][64], sdt[2][8], sdA[2][8];
    float h[64];
#pragma unroll
    for (int n = 0; n < 64; n++) h[n] = 0.f;
    float Dh = Dp[hh];
    size_t base = (size_t)s * L;

    // preload step 0
    float pf_x   = xbc[base * CONVD + tid];
    float pf_aux = 0.f;
    if (tid < 128)       pf_aux = xbc[base * CONVD + DIN + tid];
    else if (tid < 136)  pf_aux = dt[base * HEADS + (tid - 128)];
    else if (tid < 144)  pf_aux = dA[base * HEADS + (tid - 136)];

    for (int l = 0; l < L; ++l) {
        int buf = l & 1;
        if (tid < 64)        sB[buf][tid] = pf_aux;
        else if (tid < 128)  sC[buf][tid - 64] = pf_aux;
        else if (tid < 136)  sdt[buf][tid - 128] = pf_aux;
        else if (tid < 144)  sdA[buf][tid - 136] = pf_aux;
        float xv = pf_x;
        __syncthreads();
        // prefetch step l+1 while computing step l (hidden behind FMA block)
        if (l + 1 < L) {
            size_t nb = base + l + 1;
            pf_x = xbc[nb * CONVD + tid];
            if (tid < 128)       pf_aux = xbc[nb * CONVD + DIN + tid];
            else if (tid < 136)  pf_aux = dt[nb * HEADS + (tid - 128)];
            else if (tid < 144)  pf_aux = dA[nb * HEADS + (tid - 136)];
        }
        float a   = sdA[buf][hh];
        float xdt = xv * sdt[buf][hh];
        float acc0 = 0.f, acc1 = 0.f, acc2 = 0.f, acc3 = 0.f;
#pragma unroll
        for (int n4 = 0; n4 < 16; ++n4) {
            float4 b4 = *(const float4*)&sB[buf][n4 * 4];
            float4 c4 = *(const float4*)&sC[buf][n4 * 4];
            int n = n4 * 4;
            h[n+0] = fmaf(a, h[n+0], xdt * b4.x); acc0 = fmaf(h[n+0], c4.x, acc0);
            h[n+1] = fmaf(a, h[n+1], xdt * b4.y); acc1 = fmaf(h[n+1], c4.y, acc1);
            h[n+2] = fmaf(a, h[n+2], xdt * b4.z); acc2 = fmaf(h[n+2], c4.z, acc2);
            h[n+3] = fmaf(a, h[n+3], xdt * b4.w); acc3 = fmaf(h[n+3], c4.w, acc3);
        }
        y[(base + l) * DIN + tid] = ((acc0 + acc1) + (acc2 + acc3)) + Dh * xv;
    }
}

// ---- gate (y * silu(z)) + rmsnorm-512 -> bf16 hi/lo : one warp / token ----
__global__ __launch_bounds__(256) void gate_k(const float* __restrict__ y,
                                              const float* __restrict__ zx,
                                              const float* __restrict__ gn,
                                              __nv_bfloat16* __restrict__ oh,
                                              __nv_bfloat16* __restrict__ ol)
{
    int warp = (blockIdx.x * blockDim.x + threadIdx.x) >> 5;
    int lane = threadIdx.x & 31;
    const float* yrow = y  + (size_t)warp * DIN;
    const float* zrow = zx + (size_t)warp * ZROW;
    float v[16]; float ss = 0.f;
#pragma unroll
    for (int i = 0; i < 16; i++) {
        int c = lane + i*32;
        float z  = zrow[c];
        float gv = yrow[c] * (z / (1.f + __expf(-z)));
        v[i] = gv; ss += gv * gv;
    }
#pragma unroll
    for (int o = 16; o > 0; o >>= 1) ss += __shfl_xor_sync(0xffffffffu, ss, o);
    float rs = rsqrtf(ss * (1.f/512.f) + 1e-6f);
    __nv_bfloat16* hrow = oh + (size_t)warp * DIN;
    __nv_bfloat16* lrow = ol + (size_t)warp * DIN;
#pragma unroll
    for (int i = 0; i < 16; i++) {
        int c = lane + i*32;
        float f = v[i] * rs * gn[c];
        __nv_bfloat16 h = __float2bfloat16(f);
        hrow[c] = h;
        lrow[c] = __float2bfloat16(f - __bfloat162float(h));
    }
}

// ---------------- transpose (2,64,512,H) -> (2,512,64,H) ----------------
__global__ __launch_bounds__(256) void transpose_k(const float* __restrict__ in,
                                                   float* __restrict__ out)
{
    size_t id = (size_t)blockIdx.x * 256 + threadIdx.x;
    int h4   = (int)(id & 63);
    int band = (int)((id >> 6) & 63);
    int t    = (int)((id >> 12) & 511);
    int b    = (int)(id >> 21);
    const float4* ip = (const float4*)in;
    ((float4*)out)[id] = ip[((((size_t)(b * 64 + band)) * 512 + t) << 6) + h4];
}

// ---------------- host-side orchestration ----------------
static void run_mamba(const float* io_in, float* io_out, int S, int L,
                      const float* norm, const float* Wdt,
                      const __nv_bfloat16* WinTh, const __nv_bfloat16* WinTl,
                      const float* cw, const float* cb, const float* dtb,
                      const float* Alog, const float* Dp, const float* gn,
                      const __nv_bfloat16* WoutTh, const __nv_bfloat16* WoutTl,
                      __nv_bfloat16* xh, __nv_bfloat16* xl,
                      float* zx, float* xbc, float* dtp, float* dAp, float* yb)
{
    rms256_k<<<TOK / 8, 256>>>(io_in, norm, Wdt, dtb, Alog, xh, xl, dtp, dAp);
    {
        dim3 grid(ZROW / 128, TOK / 128);
        mma_gemm_k<<<grid, 256, GEMM_SMEM>>>(ZROW, HDIM, xh, xl, WinTh, WinTl, nullptr, zx);
    }
    {
        int nch = L / 64;
        dim3 grid(S * nch, CONVD / 128);
        conv_k<<<grid, 128>>>(zx, cw, cb, xbc, L, nch);
    }
    scan_k<<<S, 512>>>(xbc, dtp, dAp, Dp, yb, L);
    gate_k<<<TOK / 8, 256>>>(yb, zx, gn, xh, xl);
    {
        dim3 grid(HDIM / 128, TOK / 128);
        mma_gemm_k<<<grid, 256, GEMM_SMEM>>>(HDIM, DIN, xh, xl, WoutTh, WoutTl, io_in, io_out);
    }
}

extern "C" void kernel_launch(void* const* d_in, const int* in_sizes, int n_in,
                              void* d_out, int out_size)
{
    const float* x = (const float*)d_in[0];
    const float* prm[2][9];
    for (int pth = 0; pth < 2; ++pth)
        for (int j = 0; j < 9; ++j)
            prm[pth][j] = (const float*)d_in[1 + pth * 9 + j];
    // order per path: norm, Win, cw, cb, dtb, Alog, D, gn, Wout

    cudaFuncSetAttribute(mma_gemm_k, cudaFuncAttributeMaxDynamicSharedMemorySize, GEMM_SMEM);

    float *bufA, *bufB, *zx, *xbc, *dtp, *dAp, *yb, *Wdt;
    __nv_bfloat16 *xh, *xl, *WinTh, *WinTl, *WoutTh, *WoutTl;
    cudaGetSymbolAddress((void**)&bufA, g_bufA);
    cudaGetSymbolAddress((void**)&bufB, g_bufB);
    cudaGetSymbolAddress((void**)&zx,  g_zx);
    cudaGetSymbolAddress((void**)&xbc, g_xbc);
    cudaGetSymbolAddress((void**)&dtp, g_dt);
    cudaGetSymbolAddress((void**)&dAp, g_dA);
    cudaGetSymbolAddress((void**)&yb,  g_y);
    cudaGetSymbolAddress((void**)&xh,  g_xh);
    cudaGetSymbolAddress((void**)&xl,  g_xl);
    cudaGetSymbolAddress((void**)&WinTh,  g_WinTh);
    cudaGetSymbolAddress((void**)&WinTl,  g_WinTl);
    cudaGetSymbolAddress((void**)&WoutTh, g_WoutTh);
    cudaGetSymbolAddress((void**)&WoutTl, g_WoutTl);
    cudaGetSymbolAddress((void**)&Wdt, g_Wdt);

    // weight prep: 2 launches => rms256 is my #3, in-proj GEMM my #4 (ncu target)
    {
        size_t tot = 12ull * ZROW * HDIM;
        wtrans_win_k<<<(unsigned)((tot + 255) / 256), 256>>>(prm[0][1], prm[1][1], WinTh, WinTl);
    }
    {
        size_t tot = 12ull * HDIM * DIN + 12ull * HDIM * HEADS;
        wtrans_misc_k<<<(unsigned)((tot + 255) / 256), 256>>>(
            prm[0][8], prm[1][8], prm[0][1], prm[1][1], WoutTh, WoutTl, Wdt);
    }

    float* cur = bufA;
    float* alt = bufB;
    const size_t nF4 = XELEMS / 4;

    for (int i = 0; i < NL; ++i) {
        // time path: 128 contiguous sequences of 512 tokens
        const float* tin = (i == 0) ? x : cur;
        run_mamba(tin, cur, 128, 512,
                  prm[0][0] + (size_t)i * HDIM,
                  Wdt + (size_t)(0 * NL + i) * HDIM * HEADS,
                  WinTh + (size_t)(0 * NL + i) * ZROW * HDIM,
                  WinTl + (size_t)(0 * NL + i) * ZROW * HDIM,
                  prm[0][2] + (size_t)i * 4 * CONVD,
                  prm[0][3] + (size_t)i * CONVD,
                  prm[0][4] + (size_t)i * HEADS,
                  prm[0][5] + (size_t)i * HEADS,
                  prm[0][6] + (size_t)i * HEADS,
                  prm[0][7] + (size_t)i * DIN,
                  WoutTh + (size_t)(0 * NL + i) * HDIM * DIN,
                  WoutTl + (size_t)(0 * NL + i) * HDIM * DIN,
                  xh, xl, zx, xbc, dtp, dAp, yb);

        transpose_k<<<(unsigned)(nF4 / 256), 256>>>(cur, alt);
        { float* tmp = cur; cur = alt; alt = tmp; }

        // band path: 1024 contiguous sequences of 64 tokens
        float* bout = (i == NL - 1) ? (float*)d_out : cur;
        run_mamba(cur, bout, 1024, 64,
                  prm[1][0] + (size_t)i * HDIM,
                  Wdt + (size_t)(1 * NL + i) * HDIM * HEADS,
                  WinTh + (size_t)(1 * NL + i) * ZROW * HDIM,
                  WinTl + (size_t)(1 * NL + i) * ZROW * HDIM,
                  prm[1][2] + (size_t)i * 4 * CONVD,
                  prm[1][3] + (size_t)i * CONVD,
                  prm[1][4] + (size_t)i * HEADS,
                  prm[1][5] + (size_t)i * HEADS,
                  prm[1][6] + (size_t)i * HEADS,
                  prm[1][7] + (size_t)i * DIN,
                  WoutTh + (size_t)(1 * NL + i) * HDIM * DIN,
                  WoutTl + (size_t)(1 * NL + i) * HDIM * DIN,
                  xh, xl, zx, xbc, dtp, dAp, yb);
    }
}

// round 16
// speedup vs baseline: 1.1047x; 1.0075x over previous
#include <cuda_runtime.h>
#include <cuda_bf16.h>
#include <math.h>
#include <stdint.h>

// ---------------- problem constants ----------------
#define HDIM   256
#define NL     6
#define NSTATE 64
#define DIN    512
#define HEADS  8
#define PDIM   64
#define CONVD  640          // DIN + 2*N
#define PROJ   1160         // full in-proj width (source layout)
#define ZROW   1152         // z(512) + xBC(640) -> GEMM output width, 9 tiles of 128
#define TOK    65536        // tokens per mamba call (128*512 == 1024*64)
#define XELEMS (2ull*512ull*64ull*HDIM)   // 16,777,216

// ---------------- scratch (device globals; no allocation allowed) ----------------
__device__ float g_bufA[XELEMS];
__device__ float g_bufB[XELEMS];
__device__ float g_zx [(size_t)TOK * ZROW];
__device__ float g_xbc[(size_t)TOK * CONVD];
__device__ float g_dt [(size_t)TOK * HEADS];
__device__ float g_dA [(size_t)TOK * HEADS];
__device__ float g_y  [(size_t)TOK * DIN];
__device__ __nv_bfloat16 g_xh[(size_t)TOK * DIN];
__device__ __nv_bfloat16 g_xl[(size_t)TOK * DIN];
__device__ __nv_bfloat16 g_WinTh [12][(size_t)ZROW * HDIM];
__device__ __nv_bfloat16 g_WinTl [12][(size_t)ZROW * HDIM];
__device__ __nv_bfloat16 g_WoutTh[12][(size_t)HDIM * DIN];
__device__ __nv_bfloat16 g_WoutTl[12][(size_t)HDIM * DIN];
__device__ float g_Wdt[12][(size_t)HDIM * HEADS];   // dt columns, [k][h] fp32

// ================= PTX helpers (baseline ISA only) =================
__device__ __forceinline__ uint32_t smem_u32(const void* p) {
    uint32_t a;
    asm("{ .reg .u64 t; cvta.to.shared.u64 t, %1; cvt.u32.u64 %0, t; }" : "=r"(a) : "l"(p));
    return a;
}
#define CP_ASYNC16(dst, src) \
    asm volatile("cp.async.cg.shared.global [%0], [%1], 16;" :: "r"(dst), "l"(src))
#define CP_COMMIT() asm volatile("cp.async.commit_group;" ::: "memory")
#define CP_WAIT0()  asm volatile("cp.async.wait_group 0;" ::: "memory")
#define CP_WAIT1()  asm volatile("cp.async.wait_group 1;" ::: "memory")
#define LDSM_X4(r0, r1, r2, r3, addr) \
    asm volatile("ldmatrix.sync.aligned.m8n8.x4.shared.b16 {%0,%1,%2,%3}, [%4];" \
        : "=r"(r0), "=r"(r1), "=r"(r2), "=r"(r3) : "r"(addr))
#define MMA_BF16(d, a, b) \
    asm volatile("mma.sync.aligned.m16n8k16.row.col.f32.bf16.bf16.f32 " \
        "{%0,%1,%2,%3}, {%4,%5,%6,%7}, {%8,%9}, {%0,%1,%2,%3};" \
        : "+f"((d)[0]), "+f"((d)[1]), "+f"((d)[2]), "+f"((d)[3]) \
        : "r"((a)[0]), "r"((a)[1]), "r"((a)[2]), "r"((a)[3]), \
          "r"((b)[0]), "r"((b)[1]))
// packed f32x2 (Blackwell; ptxas never auto-fuses -- SASS_QUICKREF patterns)
#define MUL2(d, a, b) \
    asm("mul.rn.f32x2 %0, %1, %2;" : "=l"(d) : "l"(a), "l"(b))
#define FMA2(d, a, b, c) \
    asm("fma.rn.f32x2 %0, %1, %2, %3;" : "=l"(d) : "l"(a), "l"(b), "l"(c))
#define PACK2(d, v) \
    asm("mov.b64 %0, {%1, %1};" : "=l"(d) : "r"(__float_as_uint(v)))

__device__ __forceinline__ uint32_t swz(uint32_t off) { return off ^ ((off >> 3) & 0x70); }

// ================= bf16x3 HMMA GEMM =================
// C[M,N] = (Res?) + (Ah+Al)[M,K] @ (Bh+Bl)[N,K]^T, dropping Al*Bl.
// tile 128x128, K-chunk 64, cp.async 2-stage, 256 threads (2x4 warps, 64x32/warp).
#define GEMM_SMEM (2 * 65536)
__global__ __launch_bounds__(256, 1) void mma_gemm_k(int N, int K,
        const __nv_bfloat16* __restrict__ Ah, const __nv_bfloat16* __restrict__ Al,
        const __nv_bfloat16* __restrict__ Bh, const __nv_bfloat16* __restrict__ Bl,
        const float* __restrict__ Res, float* __restrict__ C)
{
    extern __shared__ __align__(1024) char smem[];
    uint32_t sb = smem_u32(smem);
    int tid  = threadIdx.x;
    int wid  = tid >> 5, lane = tid & 31;
    size_t row0 = (size_t)blockIdx.y * 128;
    size_t nr0  = (size_t)blockIdx.x * 128;
    int    n0   = blockIdx.x * 128;

    const __nv_bfloat16* mats[4] = { Ah, Al, Bh, Bl };
    const int NC = K >> 6;

    auto load_stage = [&](int c) {
        uint32_t st = sb + (uint32_t)(c & 1) * 65536;
        int kofs = c << 6;
#pragma unroll
        for (int m = 0; m < 4; ++m) {
            size_t rbase = (m < 2) ? row0 : nr0;
            const char* P = (const char*)(mats[m] + rbase * K + kofs);
            uint32_t dst = st + m * 16384;
#pragma unroll
            for (int i = 0; i < 4; ++i) {
                int seg = i * 256 + tid;
                int row = seg >> 3, sj = seg & 7;
                CP_ASYNC16(dst + swz(row * 128 + sj * 16),
                           P + (size_t)row * K * 2 + sj * 16);
            }
        }
        CP_COMMIT();
    };

    float acc[4][4][4];
#pragma unroll
    for (int i = 0; i < 4; ++i)
#pragma unroll
        for (int j = 0; j < 4; ++j)
#pragma unroll
            for (int q = 0; q < 4; ++q) acc[i][j][q] = 0.f;

    int wm = wid >> 2, wn = wid & 3;      // warps 2(m) x 4(n)
    int m0w = wm * 64, n0w = wn * 32;
    int lm = lane & 7;
    int li = lane >> 3;

    load_stage(0);
    for (int c = 0; c < NC; ++c) {
        bool pf = (c + 1 < NC);
        if (pf) load_stage(c + 1);
        if (pf) CP_WAIT1(); else CP_WAIT0();
        __syncthreads();

        uint32_t st  = sb + (uint32_t)(c & 1) * 65536;
        uint32_t aph = st, apl = st + 16384, bph = st + 32768, bpl = st + 49152;
#pragma unroll
        for (int k16 = 0; k16 < 4; ++k16) {
            uint32_t Ahf[4][4], Alf[4][4], Bhf[4][2], Blf[4][2];
            {
                int rA   = m0w + ((li & 1) << 3) + lm;
                int c16A = k16 * 2 + (li >> 1);
#pragma unroll
                for (int ma = 0; ma < 4; ++ma) {
                    uint32_t off = swz((uint32_t)(rA + ma * 16) * 128 + c16A * 16);
                    LDSM_X4(Ahf[ma][0], Ahf[ma][1], Ahf[ma][2], Ahf[ma][3], aph + off);
                    LDSM_X4(Alf[ma][0], Alf[ma][1], Alf[ma][2], Alf[ma][3], apl + off);
                }
            }
            {
                int rB   = n0w + ((li >> 1) << 3) + lm;
                int c16B = k16 * 2 + (li & 1);
#pragma unroll
                for (int nb = 0; nb < 2; ++nb) {
                    uint32_t off = swz((uint32_t)(rB + nb * 16) * 128 + c16B * 16);
                    LDSM_X4(Bhf[nb*2][0], Bhf[nb*2][1], Bhf[nb*2+1][0], Bhf[nb*2+1][1], bph + off);
                    LDSM_X4(Blf[nb*2][0], Blf[nb*2][1], Blf[nb*2+1][0], Blf[nb*2+1][1], bpl + off);
                }
            }
#pragma unroll
            for (int ma = 0; ma < 4; ++ma)
#pragma unroll
                for (int na = 0; na < 4; ++na)
                    MMA_BF16(acc[ma][na], Ahf[ma], Bhf[na]);
#pragma unroll
            for (int ma = 0; ma < 4; ++ma)
#pragma unroll
                for (int na = 0; na < 4; ++na)
                    MMA_BF16(acc[ma][na], Ahf[ma], Blf[na]);
#pragma unroll
            for (int ma = 0; ma < 4; ++ma)
#pragma unroll
                for (int na = 0; na < 4; ++na)
                    MMA_BF16(acc[ma][na], Alf[ma], Bhf[na]);
        }
        __syncthreads();
    }

    int gid = lane >> 2, tig = lane & 3;
#pragma unroll
    for (int ma = 0; ma < 4; ++ma) {
        size_t r0g = row0 + m0w + ma * 16 + gid;
#pragma unroll
        for (int na = 0; na < 4; ++na) {
            int cc = n0 + n0w + na * 8 + tig * 2;
            float2 v0 = make_float2(acc[ma][na][0], acc[ma][na][1]);
            float2 v1 = make_float2(acc[ma][na][2], acc[ma][na][3]);
            if (Res) {
                float2 r0v = *(const float2*)&Res[r0g * N + cc];
                float2 r1v = *(const float2*)&Res[(r0g + 8) * N + cc];
                v0.x += r0v.x; v0.y += r0v.y; v1.x += r1v.x; v1.y += r1v.y;
            }
            *(float2*)&C[r0g * N + cc]       = v0;
            *(float2*)&C[(r0g + 8) * N + cc] = v1;
        }
    }
}

// ------- weight prep: exactly 2 launches -------
__global__ __launch_bounds__(256) void wtrans_win_k(const float* __restrict__ Wt,
                                                    const float* __restrict__ Wb,
                                                    __nv_bfloat16* __restrict__ WTh,
                                                    __nv_bfloat16* __restrict__ WTl)
{
    size_t idx = (size_t)blockIdx.x * 256 + threadIdx.x;
    if (idx >= 12ull * ZROW * HDIM) return;
    int li  = (int)(idx / ((size_t)ZROW * HDIM));
    int rem = (int)(idx % ((size_t)ZROW * HDIM));
    int n = rem / HDIM, k = rem % HDIM;
    const float* W = (li < 6) ? (Wt + (size_t)li * HDIM * PROJ)
                              : (Wb + (size_t)(li - 6) * HDIM * PROJ);
    float v = W[(size_t)k * PROJ + n];
    __nv_bfloat16 h = __float2bfloat16(v);
    WTh[idx] = h;
    WTl[idx] = __float2bfloat16(v - __bfloat162float(h));
}
__global__ __launch_bounds__(256) void wtrans_misc_k(const float* __restrict__ WtO,
                                                     const float* __restrict__ WbO,
                                                     const float* __restrict__ WtI,
                                                     const float* __restrict__ WbI,
                                                     __nv_bfloat16* __restrict__ WTh,
                                                     __nv_bfloat16* __restrict__ WTl,
                                                     float* __restrict__ Wdt)
{
    size_t woutTot = 12ull * HDIM * DIN;
    size_t idx = (size_t)blockIdx.x * 256 + threadIdx.x;
    if (idx < woutTot) {
        int li  = (int)(idx / ((size_t)HDIM * DIN));
        int rem = (int)(idx % ((size_t)HDIM * DIN));
        int n = rem / DIN, k = rem % DIN;
        const float* W = (li < 6) ? (WtO + (size_t)li * DIN * HDIM)
                                  : (WbO + (size_t)(li - 6) * DIN * HDIM);
        float v = W[(size_t)k * HDIM + n];
        __nv_bfloat16 h = __float2bfloat16(v);
        WTh[idx] = h;
        WTl[idx] = __float2bfloat16(v - __bfloat162float(h));
    } else {
        size_t j = idx - woutTot;
        if (j >= 12ull * HDIM * HEADS) return;
        int li  = (int)(j / (HDIM * HEADS));
        int rem = (int)(j % (HDIM * HEADS));
        int k = rem / HEADS, h = rem % HEADS;
        const float* W = (li < 6) ? (WtI + (size_t)li * HDIM * PROJ)
                                  : (WbI + (size_t)(li - 6) * HDIM * PROJ);
        Wdt[j] = W[(size_t)k * PROJ + ZROW + h];
    }
}

// ------ rmsnorm-256 -> bf16 hi/lo  +  fused dt/dA (fp32 GEMV over 8 cols) ------
__global__ __launch_bounds__(256) void rms256_k(const float* __restrict__ x,
                                                const float* __restrict__ w,
                                                const float* __restrict__ Wdt,
                                                const float* __restrict__ dtb,
                                                const float* __restrict__ Alog,
                                                __nv_bfloat16* __restrict__ oh,
                                                __nv_bfloat16* __restrict__ ol,
                                                float* __restrict__ odt,
                                                float* __restrict__ odA)
{
    int warp = (blockIdx.x * blockDim.x + threadIdx.x) >> 5;   // token
    int lane = threadIdx.x & 31;
    const float* row = x + (size_t)warp * HDIM;
    float v[8]; float ss = 0.f;
#pragma unroll
    for (int i = 0; i < 8; i++) { v[i] = row[lane + i*32]; ss += v[i]*v[i]; }
#pragma unroll
    for (int o = 16; o > 0; o >>= 1) ss += __shfl_xor_sync(0xffffffffu, ss, o);
    float rs = rsqrtf(ss * (1.f/256.f) + 1e-6f);
    __nv_bfloat16* hrow = oh + (size_t)warp * HDIM;
    __nv_bfloat16* lrow = ol + (size_t)warp * HDIM;
    float ph[8];
#pragma unroll
    for (int q = 0; q < 8; q++) ph[q] = 0.f;
#pragma unroll
    for (int i = 0; i < 8; i++) {
        int c = lane + i*32;
        float f = v[i] * rs * w[c];
        __nv_bfloat16 h = __float2bfloat16(f);
        hrow[c] = h;
        lrow[c] = __float2bfloat16(f - __bfloat162float(h));
        const float* wd = Wdt + c * HEADS;
        float4 wa = *(const float4*)wd;
        float4 wb = *(const float4*)(wd + 4);
        ph[0] = fmaf(f, wa.x, ph[0]); ph[1] = fmaf(f, wa.y, ph[1]);
        ph[2] = fmaf(f, wa.z, ph[2]); ph[3] = fmaf(f, wa.w, ph[3]);
        ph[4] = fmaf(f, wb.x, ph[4]); ph[5] = fmaf(f, wb.y, ph[5]);
        ph[6] = fmaf(f, wb.z, ph[6]); ph[7] = fmaf(f, wb.w, ph[7]);
    }
#pragma unroll
    for (int o = 16; o > 0; o >>= 1)
#pragma unroll
        for (int q = 0; q < 8; q++) ph[q] += __shfl_xor_sync(0xffffffffu, ph[q], o);
    if (lane == 0) {
#pragma unroll
        for (int q = 0; q < 8; q++) {
            float raw = ph[q] + dtb[q];
            float sp  = (raw > 20.f) ? raw : log1pf(expf(raw));
            odt[(size_t)warp * HEADS + q] = sp;
            odA[(size_t)warp * HEADS + q] = expf(-expf(Alog[q]) * sp);
        }
    }
}

// ------- causal depthwise conv (k=4) + SiLU, parallel over 64-step L-chunks -------
__global__ __launch_bounds__(128) void conv_k(const float* __restrict__ zx,
                                              const float* __restrict__ cw,
                                              const float* __restrict__ cb,
                                              float* __restrict__ xbc,
                                              int L, int nch)
{
    int bx = blockIdx.x;
    int s  = bx / nch;
    int ch = bx - s * nch;
    int c  = blockIdx.y * 128 + threadIdx.x;      // 0..639
    int l0 = ch * 64;
    float w0 = cw[c], w1 = cw[640 + c], w2 = cw[1280 + c], w3 = cw[1920 + c];
    float bias = cb[c];
    const float* in  = zx  + ((size_t)s * L + l0) * ZROW + DIN + c;
    float*       out = xbc + ((size_t)s * L + l0) * CONVD + c;
    float x0 = (l0 > 0) ? in[-3 * ZROW] : 0.f;
    float x1 = (l0 > 0) ? in[-2 * ZROW] : 0.f;
    float x2 = (l0 > 0) ? in[-1 * ZROW] : 0.f;
    for (int l = 0; l < 64; ++l) {
        float x3 = in[(size_t)l * ZROW];
        float v  = bias + w0*x0 + w1*x1 + w2*x2 + w3*x3;
        out[(size_t)l * CONVD] = v / (1.f + __expf(-v));
        x0 = x1; x1 = x2; x2 = x3;
    }
}

// ------- SSM scan, packed f32x2 inner loop, next-step prefetch -------
__global__ __launch_bounds__(512, 1) void scan_k(const float* __restrict__ xbc,
                                                 const float* __restrict__ dt,
                                                 const float* __restrict__ dA,
                                                 const float* __restrict__ Dp,
                                                 float* __restrict__ y,
                                                 int L)
{
    int s   = blockIdx.x;
    int tid = threadIdx.x;
    int hh  = tid >> 6;
    __shared__ __align__(16) float sB[2][64], sC[2][64];
    __shared__ float sdt[2][8], sdA[2][8];
    uint64_t h2[32];
#pragma unroll
    for (int n = 0; n < 32; n++) h2[n] = 0ull;      // (0.f, 0.f)
    float Dh = Dp[hh];
    size_t base = (size_t)s * L;

    // preload step 0
    float pf_x   = xbc[base * CONVD + tid];
    float pf_aux = 0.f;
    if (tid < 128)       pf_aux = xbc[base * CONVD + DIN + tid];
    else if (tid < 136)  pf_aux = dt[base * HEADS + (tid - 128)];
    else if (tid < 144)  pf_aux = dA[base * HEADS + (tid - 136)];

    for (int l = 0; l < L; ++l) {
        int buf = l & 1;
        if (tid < 64)        sB[buf][tid] = pf_aux;
        else if (tid < 128)  sC[buf][tid - 64] = pf_aux;
        else if (tid < 136)  sdt[buf][tid - 128] = pf_aux;
        else if (tid < 144)  sdA[buf][tid - 136] = pf_aux;
        float xv = pf_x;
        __syncthreads();
        // prefetch step l+1 while computing step l
        if (l + 1 < L) {
            size_t nb = base + l + 1;
            pf_x = xbc[nb * CONVD + tid];
            if (tid < 128)       pf_aux = xbc[nb * CONVD + DIN + tid];
            else if (tid < 136)  pf_aux = dt[nb * HEADS + (tid - 128)];
            else if (tid < 144)  pf_aux = dA[nb * HEADS + (tid - 136)];
        }
        float a   = sdA[buf][hh];
        float xdt = xv * sdt[buf][hh];
        uint64_t a2, x2;
        PACK2(a2, a);
        PACK2(x2, xdt);
        uint64_t ac0 = 0ull, ac1 = 0ull, ac2 = 0ull, ac3 = 0ull;
#pragma unroll
        for (int n4 = 0; n4 < 16; ++n4) {
            ulonglong2 b2 = *(const ulonglong2*)&sB[buf][n4 * 4];   // 2 packed pairs
            ulonglong2 c2 = *(const ulonglong2*)&sC[buf][n4 * 4];
            uint64_t t0, t1;
            MUL2(t0, x2, b2.x);
            MUL2(t1, x2, b2.y);
            FMA2(h2[n4*2],   a2, h2[n4*2],   t0);
            FMA2(h2[n4*2+1], a2, h2[n4*2+1], t1);
            if (n4 & 1) {
                FMA2(ac2, h2[n4*2],   c2.x, ac2);
                FMA2(ac3, h2[n4*2+1], c2.y, ac3);
            } else {
                FMA2(ac0, h2[n4*2],   c2.x, ac0);
                FMA2(ac1, h2[n4*2+1], c2.y, ac1);
            }
        }
        uint32_t u0, u1, u2, u3, u4, u5, u6, u7;
        asm("mov.b64 {%0, %1}, %2;" : "=r"(u0), "=r"(u1) : "l"(ac0));
        asm("mov.b64 {%0, %1}, %2;" : "=r"(u2), "=r"(u3) : "l"(ac1));
        asm("mov.b64 {%0, %1}, %2;" : "=r"(u4), "=r"(u5) : "l"(ac2));
        asm("mov.b64 {%0, %1}, %2;" : "=r"(u6), "=r"(u7) : "l"(ac3));
        float acc = ((__uint_as_float(u0) + __uint_as_float(u1)) +
                     (__uint_as_float(u2) + __uint_as_float(u3))) +
                    ((__uint_as_float(u4) + __uint_as_float(u5)) +
                     (__uint_as_float(u6) + __uint_as_float(u7)));
        y[(base + l) * DIN + tid] = acc + Dh * xv;
    }
}

// ---- gate (y * silu(z)) + rmsnorm-512 -> bf16 hi/lo : one warp / token ----
__global__ __launch_bounds__(256) void gate_k(const float* __restrict__ y,
                                              const float* __restrict__ zx,
                                              const float* __restrict__ gn,
                                              __nv_bfloat16* __restrict__ oh,
                                              __nv_bfloat16* __restrict__ ol)
{
    int warp = (blockIdx.x * blockDim.x + threadIdx.x) >> 5;
    int lane = threadIdx.x & 31;
    const float* yrow = y  + (size_t)warp * DIN;
    const float* zrow = zx + (size_t)warp * ZROW;
    float v[16]; float ss = 0.f;
#pragma unroll
    for (int i = 0; i < 16; i++) {
        int c = lane + i*32;
        float z  = zrow[c];
        float gv = yrow[c] * (z / (1.f + __expf(-z)));
        v[i] = gv; ss += gv * gv;
    }
#pragma unroll
    for (int o = 16; o > 0; o >>= 1) ss += __shfl_xor_sync(0xffffffffu, ss, o);
    float rs = rsqrtf(ss * (1.f/512.f) + 1e-6f);
    __nv_bfloat16* hrow = oh + (size_t)warp * DIN;
    __nv_bfloat16* lrow = ol + (size_t)warp * DIN;
#pragma unroll
    for (int i = 0; i < 16; i++) {
        int c = lane + i*32;
        float f = v[i] * rs * gn[c];
        __nv_bfloat16 h = __float2bfloat16(f);
        hrow[c] = h;
        lrow[c] = __float2bfloat16(f - __bfloat162float(h));
    }
}

// ---------------- transpose (2,64,512,H) -> (2,512,64,H) ----------------
__global__ __launch_bounds__(256) void transpose_k(const float* __restrict__ in,
                                                   float* __restrict__ out)
{
    size_t id = (size_t)blockIdx.x * 256 + threadIdx.x;
    int h4   = (int)(id & 63);
    int band = (int)((id >> 6) & 63);
    int t    = (int)((id >> 12) & 511);
    int b    = (int)(id >> 21);
    const float4* ip = (const float4*)in;
    ((float4*)out)[id] = ip[((((size_t)(b * 64 + band)) * 512 + t) << 6) + h4];
}

// ---------------- host-side orchestration ----------------
static void run_mamba(const float* io_in, float* io_out, int S, int L,
                      const float* norm, const float* Wdt,
                      const __nv_bfloat16* WinTh, const __nv_bfloat16* WinTl,
                      const float* cw, const float* cb, const float* dtb,
                      const float* Alog, const float* Dp, const float* gn,
                      const __nv_bfloat16* WoutTh, const __nv_bfloat16* WoutTl,
                      __nv_bfloat16* xh, __nv_bfloat16* xl,
                      float* zx, float* xbc, float* dtp, float* dAp, float* yb)
{
    rms256_k<<<TOK / 8, 256>>>(io_in, norm, Wdt, dtb, Alog, xh, xl, dtp, dAp);
    {
        dim3 grid(ZROW / 128, TOK / 128);
        mma_gemm_k<<<grid, 256, GEMM_SMEM>>>(ZROW, HDIM, xh, xl, WinTh, WinTl, nullptr, zx);
    }
    {
        int nch = L / 64;
        dim3 grid(S * nch, CONVD / 128);
        conv_k<<<grid, 128>>>(zx, cw, cb, xbc, L, nch);
    }
    scan_k<<<S, 512>>>(xbc, dtp, dAp, Dp, yb, L);
    gate_k<<<TOK / 8, 256>>>(yb, zx, gn, xh, xl);
    {
        dim3 grid(HDIM / 128, TOK / 128);
        mma_gemm_k<<<grid, 256, GEMM_SMEM>>>(HDIM, DIN, xh, xl, WoutTh, WoutTl, io_in, io_out);
    }
}

extern "C" void kernel_launch(void* const* d_in, const int* in_sizes, int n_in,
                              void* d_out, int out_size)
{
    const float* x = (const float*)d_in[0];
    const float* prm[2][9];
    for (int pth = 0; pth < 2; ++pth)
        for (int j = 0; j < 9; ++j)
            prm[pth][j] = (const float*)d_in[1 + pth * 9 + j];
    // order per path: norm, Win, cw, cb, dtb, Alog, D, gn, Wout

    cudaFuncSetAttribute(mma_gemm_k, cudaFuncAttributeMaxDynamicSharedMemorySize, GEMM_SMEM);

    float *bufA, *bufB, *zx, *xbc, *dtp, *dAp, *yb, *Wdt;
    __nv_bfloat16 *xh, *xl, *WinTh, *WinTl, *WoutTh, *WoutTl;
    cudaGetSymbolAddress((void**)&bufA, g_bufA);
    cudaGetSymbolAddress((void**)&bufB, g_bufB);
    cudaGetSymbolAddress((void**)&zx,  g_zx);
    cudaGetSymbolAddress((void**)&xbc, g_xbc);
    cudaGetSymbolAddress((void**)&dtp, g_dt);
    cudaGetSymbolAddress((void**)&dAp, g_dA);
    cudaGetSymbolAddress((void**)&yb,  g_y);
    cudaGetSymbolAddress((void**)&xh,  g_xh);
    cudaGetSymbolAddress((void**)&xl,  g_xl);
    cudaGetSymbolAddress((void**)&WinTh,  g_WinTh);
    cudaGetSymbolAddress((void**)&WinTl,  g_WinTl);
    cudaGetSymbolAddress((void**)&WoutTh, g_WoutTh);
    cudaGetSymbolAddress((void**)&WoutTl, g_WoutTl);
    cudaGetSymbolAddress((void**)&Wdt, g_Wdt);

    // weight prep: 2 launches => rms256 is my #3, in-proj GEMM my #4 (ncu target)
    {
        size_t tot = 12ull * ZROW * HDIM;
        wtrans_win_k<<<(unsigned)((tot + 255) / 256), 256>>>(prm[0][1], prm[1][1], WinTh, WinTl);
    }
    {
        size_t tot = 12ull * HDIM * DIN + 12ull * HDIM * HEADS;
        wtrans_misc_k<<<(unsigned)((tot + 255) / 256), 256>>>(
            prm[0][8], prm[1][8], prm[0][1], prm[1][1], WoutTh, WoutTl, Wdt);
    }

    float* cur = bufA;
    float* alt = bufB;
    const size_t nF4 = XELEMS / 4;

    for (int i = 0; i < NL; ++i) {
        // time path: 128 contiguous sequences of 512 tokens
        const float* tin = (i == 0) ? x : cur;
        run_mamba(tin, cur, 128, 512,
                  prm[0][0] + (size_t)i * HDIM,
                  Wdt + (size_t)(0 * NL + i) * HDIM * HEADS,
                  WinTh + (size_t)(0 * NL + i) * ZROW * HDIM,
                  WinTl + (size_t)(0 * NL + i) * ZROW * HDIM,
                  prm[0][2] + (size_t)i * 4 * CONVD,
                  prm[0][3] + (size_t)i * CONVD,
                  prm[0][4] + (size_t)i * HEADS,
                  prm[0][5] + (size_t)i * HEADS,
                  prm[0][6] + (size_t)i * HEADS,
                  prm[0][7] + (size_t)i * DIN,
                  WoutTh + (size_t)(0 * NL + i) * HDIM * DIN,
                  WoutTl + (size_t)(0 * NL + i) * HDIM * DIN,
                  xh, xl, zx, xbc, dtp, dAp, yb);

        transpose_k<<<(unsigned)(nF4 / 256), 256>>>(cur, alt);
        { float* tmp = cur; cur = alt; alt = tmp; }

        // band path: 1024 contiguous sequences of 64 tokens
        float* bout = (i == NL - 1) ? (float*)d_out : cur;
        run_mamba(cur, bout, 1024, 64,
                  prm[1][0] + (size_t)i * HDIM,
                  Wdt + (size_t)(1 * NL + i) * HDIM * HEADS,
                  WinTh + (size_t)(1 * NL + i) * ZROW * HDIM,
                  WinTl + (size_t)(1 * NL + i) * ZROW * HDIM,
                  prm[1][2] + (size_t)i * 4 * CONVD,
                  prm[1][3] + (size_t)i * CONVD,
                  prm[1][4] + (size_t)i * HEADS,
                  prm[1][5] + (size_t)i * HEADS,
                  prm[1][6] + (size_t)i * HEADS,
                  prm[1][7] + (size_t)i * DIN,
                  WoutTh + (size_t)(1 * NL + i) * HDIM * DIN,
                  WoutTl + (size_t)(1 * NL + i) * HDIM * DIN,
                  xh, xl, zx, xbc, dtp, dAp, yb);
    }
}